// round 17
// baseline (speedup 1.0000x reference)
#include <cuda_runtime.h>

// FourierKANAdapter: out[t,d] = x[t,d] + c0[d] + sum_{k=1..3} sin(kx)*cs[d,k] + cos(kx)*cc[d,k]
// T=32768, DIM=1024, K=3. coeffs layout: [DIM][7]
//
// R17: residency levers dead (R15/R16); occupancy/vector/wave levers dead
// (R4/R7/R13 all ~42.5-43.5us kernel). Last structural lever: DRAM locality.
// Replace the strided persistent loop (g += 592 -> 1184 scattered r/w streams
// chip-wide) with CONTIGUOUS per-CTA spans (~28 groups = ~224KB sequential
// read + write per CTA) to maximize HBM row-buffer hits and give the memory
// controller long same-direction bursts.
// Balanced split: 16384 = 592*27 + 400 -> CTAs 0..399 own 28 groups,
// CTAs 400..591 own 27.

#define KAN_T    32768
#define KAN_DIM  1024
#define ROWS_PER_G  2
#define N_GROUPS (KAN_T / ROWS_PER_G)       // 16384
#define N_CTAS   (148 * 4)                  // 592: one full wave at 4 CTA/SM
#define G_BASE   (N_GROUPS / N_CTAS)        // 27
#define G_REM    (N_GROUPS % N_CTAS)        // 400

__device__ __forceinline__ float2 kan2(float2 v,
                                       const float c0[2],  const float cs1[2],
                                       const float cc1[2], const float cs2[2],
                                       const float cc2[2], const float cs3[2],
                                       const float cc3[2])
{
    const float xe[2] = {v.x, v.y};
    float oe[2];
#pragma unroll
    for (int j = 0; j < 2; j++) {
        float s1, c1;
        __sincosf(xe[j], &s1, &c1);
        float s2 = 2.0f * s1 * c1;
        float c2 = fmaf(2.0f * c1, c1, -1.0f);
        float s3 = fmaf(s1, c2, c1 * s2);
        float c3 = fmaf(c1, c2, -s1 * s2);
        float rr = fmaf(s1, cs1[j], c0[j]);
        rr = fmaf(c1, cc1[j], rr);
        rr = fmaf(s2, cs2[j], rr);
        rr = fmaf(c2, cc2[j], rr);
        rr = fmaf(s3, cs3[j], rr);
        rr = fmaf(c3, cc3[j], rr);
        oe[j] = xe[j] + rr;
    }
    return make_float2(oe[0], oe[1]);
}

__global__ __launch_bounds__(512, 4)
void fourier_kan_kernel(const float* __restrict__ x,
                        const float* __restrict__ coeffs,
                        float* __restrict__ out)
{
    const int d = threadIdx.x * 2;          // 512 threads x float2 = 1024 = DIM

    // 7 coefficients x 2 owned columns -> 14 registers.
    float c0[2], cs1[2], cc1[2], cs2[2], cc2[2], cs3[2], cc3[2];
#pragma unroll
    for (int j = 0; j < 2; j++) {
        const float* cp = coeffs + (d + j) * 7;
        c0[j]  = __ldg(cp + 0);
        cs1[j] = __ldg(cp + 1);
        cc1[j] = __ldg(cp + 2);
        cs2[j] = __ldg(cp + 3);
        cc2[j] = __ldg(cp + 4);
        cs3[j] = __ldg(cp + 5);
        cc3[j] = __ldg(cp + 6);
    }

    // Contiguous balanced span for this CTA.
    const int b       = blockIdx.x;
    const int g_start = b * G_BASE + min(b, G_REM);
    const int g_end   = g_start + G_BASE + (b < G_REM ? 1 : 0);

#pragma unroll 1
    for (int g = g_start; g < g_end; g++) {
        const size_t base = (size_t)g * (ROWS_PER_G * KAN_DIM) + d;

        // Front-batched loads: 2 independent LDG.64 in flight.
        float2 v0 = __ldcs(reinterpret_cast<const float2*>(x + base));
        float2 v1 = __ldcs(reinterpret_cast<const float2*>(x + base + KAN_DIM));

        float2 o0 = kan2(v0, c0, cs1, cc1, cs2, cc2, cs3, cc3);
        float2 o1 = kan2(v1, c0, cs1, cc1, cs2, cc2, cs3, cc3);

        __stcs(reinterpret_cast<float2*>(out + base),           o0);
        __stcs(reinterpret_cast<float2*>(out + base + KAN_DIM), o1);
    }
}

extern "C" void kernel_launch(void* const* d_in, const int* in_sizes, int n_in,
                              void* d_out, int out_size)
{
    const float* x      = (const float*)d_in[0];
    const float* coeffs = (const float*)d_in[1];
    float*       out    = (float*)d_out;

    fourier_kan_kernel<<<N_CTAS, 512>>>(x, coeffs, out);
}